// round 2
// baseline (speedup 1.0000x reference)
#include <cuda_runtime.h>

#define NN 256
#define TT 200
#define SS 100

__global__ __launch_bounds__(256)
void scan_fused_kernel(const float* __restrict__ time,
                       const float* __restrict__ ev,
                       const float* __restrict__ u_begin,
                       const float* __restrict__ a,
                       const float* __restrict__ w,
                       const float* __restrict__ lw,
                       const float* __restrict__ lb,
                       float* __restrict__ out)
{
    __shared__ float Fs[TT];

    const int n    = blockIdx.x;      // row (node) this block owns
    const int m    = threadIdx.x;     // column this thread owns
    const int lane = m & 31;
    const int wrp  = m >> 5;

    const float t0 = time[0];
    const float t1 = time[1];

    // ---------------- Phase 1: per-row factors ----------------
    // Fs[t] = exp( -dot(w[t,n,:], ev[t,n,:]) * time[t&1] )
    for (int t = wrp; t < TT; t += 8) {
        const float* wr = w  + (size_t)t * NN * NN + (size_t)n * NN;
        const float* er = ev + (size_t)t * NN * NN + (size_t)n * NN;
        float acc = 0.f;
        #pragma unroll
        for (int j = 0; j < 8; j++) {
            int k = lane + 32 * j;
            acc += wr[k] * er[k];
        }
        #pragma unroll
        for (int off = 16; off; off >>= 1)
            acc += __shfl_xor_sync(0xffffffffu, acc, off);
        if (lane == 0)
            Fs[t] = __expf(-acc * ((t & 1) ? t1 : t0));
    }
    __syncthreads();

    // ---------------- Phase 2: sequential scan, carry in registers ----------------
    const float lw0 = lw[n * 3 + 0];
    const float lw1 = lw[n * 3 + 1];
    const float lw2 = lw[n * 3 + 2];
    const float lbn = lb[n];

    const float* up = u_begin + ((size_t)n * NN + m) * 3;
    float u0 = up[0], u1 = up[1], u2 = up[2];

    const size_t NN3 = (size_t)NN * NN * 3;
    const float* ap  = a + ((size_t)n * NN + m) * 3;
    float*       op  = out + (size_t)n * NN + m;

    // prefetch step 0's two a-slices
    float a00 = ap[0],       a01 = ap[1],       a02 = ap[2];
    float a10 = ap[NN3],     a11 = ap[NN3 + 1], a12 = ap[NN3 + 2];

    for (int s = 0; s < SS; s++) {
        // software-pipelined prefetch of step s+1 (6 independent loads in flight
        // while the dependent FMA/softmax chain of step s executes)
        float b00 = 0.f, b01 = 0.f, b02 = 0.f, b10 = 0.f, b11 = 0.f, b12 = 0.f;
        if (s < SS - 1) {
            const float* nap = ap + (size_t)(2 * s + 2) * NN3;
            b00 = nap[0];       b01 = nap[1];       b02 = nap[2];
            b10 = nap[NN3];     b11 = nap[NN3 + 1]; b12 = nap[NN3 + 2];
        }

        const float f0 = Fs[2 * s];
        const float f1 = Fs[2 * s + 1];

        float l0 = u0 + a00 * f0 + a10 * f1;
        float l1 = u1 + a01 * f0 + a11 * f1;
        float l2 = u2 + a02 * f0 + a12 * f1;

        float mx = fmaxf(l0, fmaxf(l1, l2));
        float e0 = __expf(l0 - mx);
        float e1 = __expf(l1 - mx);
        float e2 = __expf(l2 - mx);
        float inv = __fdividef(1.0f, e0 + e1 + e2);

        u0 = e0 * inv;
        u1 = e1 * inv;
        u2 = e2 * inv;

        op[(size_t)s * NN * NN] = u0 * lw0 + u1 * lw1 + u2 * lw2 + lbn;

        a00 = b00; a01 = b01; a02 = b02;
        a10 = b10; a11 = b11; a12 = b12;
    }
}

extern "C" void kernel_launch(void* const* d_in, const int* in_sizes, int n_in,
                              void* d_out, int out_size)
{
    const float* time    = (const float*)d_in[0];   // [2]
    const float* ev      = (const float*)d_in[1];   // [201,256,256]
    const float* u_begin = (const float*)d_in[2];   // [256,256,3]
    const float* a       = (const float*)d_in[3];   // [200,256,256,3]
    const float* w       = (const float*)d_in[4];   // [200,256,1,256]
    const float* lw      = (const float*)d_in[5];   // [256,3]
    const float* lb      = (const float*)d_in[6];   // [256]
    // d_in[7] = batch_size (constant 2, baked into the kernel)

    float* out = (float*)d_out;                     // [100,256,256]

    scan_fused_kernel<<<NN, NN>>>(time, ev, u_begin, a, w, lw, lb, out);
}

// round 3
// speedup vs baseline: 1.1918x; 1.1918x over previous
#include <cuda_runtime.h>

#define NN 256
#define TT 200
#define SS 100
#define NSTAGE 6
#define STAGE_FLOATS (NN * 3 * 2)      // pair of slices: 1536 floats = 6144 B
#define LOOKAHEAD 5

// F[n][t] scratch (transposed so the scan kernel reads its row contiguously)
__device__ float gF[NN * TT];

// ---------------- Kernel 1: F[n][t] = exp(-dot(w[t,n,:], ev[t,n,:]) * time[t&1]) ----------------
// One warp per (t,n) dot; 8 dots per 256-thread CTA; grid = 51200/8 = 6400 CTAs.
__global__ __launch_bounds__(256)
void f_kernel(const float* __restrict__ time,
              const float* __restrict__ ev,
              const float* __restrict__ w)
{
    const int d    = blockIdx.x * 8 + (threadIdx.x >> 5);   // dot index 0..51199
    const int lane = threadIdx.x & 31;
    const int t = d >> 8;
    const int n = d & 255;

    const float4* wr = (const float4*)(w  + ((size_t)t * NN + n) * NN);
    const float4* er = (const float4*)(ev + ((size_t)t * NN + n) * NN);
    float4 w0 = wr[lane],      e0 = er[lane];
    float4 w1 = wr[lane + 32], e1 = er[lane + 32];
    float acc = w0.x*e0.x + w0.y*e0.y + w0.z*e0.z + w0.w*e0.w
              + w1.x*e1.x + w1.y*e1.y + w1.z*e1.z + w1.w*e1.w;
    #pragma unroll
    for (int off = 16; off; off >>= 1)
        acc += __shfl_xor_sync(0xffffffffu, acc, off);
    if (lane == 0)
        gF[n * TT + t] = __expf(-acc * ((t & 1) ? time[1] : time[0]));
}

// ---------------- Kernel 2: sequential scan with cp.async smem pipeline ----------------
__global__ __launch_bounds__(256)
void scan_kernel(const float* __restrict__ u_begin,
                 const float* __restrict__ a,
                 const float* __restrict__ lw,
                 const float* __restrict__ lb,
                 float* __restrict__ out)
{
    __shared__ float stages[NSTAGE][STAGE_FLOATS];   // 36864 B
    __shared__ float Fs[TT];                         // 800 B

    const int n   = blockIdx.x;     // row (node)
    const int tid = threadIdx.x;    // column m

    if (tid < TT) Fs[tid] = gF[n * TT + tid];

    const size_t slice_stride = (size_t)NN * NN * 3;     // floats from t to t+1
    const float* a_n = a + (size_t)n * NN * 3;           // a[0,n,:,:]

    // stage s holds a[2s,n,:,:] ++ a[2s+1,n,:,:]  (384 x 16B chunks)
    auto issue_stage = [&](int s) {
        char* dst = (char*)stages[s % NSTAGE];
        const char* src0 = (const char*)(a_n + (size_t)(2 * s)     * slice_stride);
        const char* src1 = (const char*)(a_n + (size_t)(2 * s + 1) * slice_stride);
        {
            int c = tid;                                  // chunks 0..255
            const char* g = (c < 192) ? (src0 + c * 16) : (src1 + (c - 192) * 16);
            unsigned sp = (unsigned)__cvta_generic_to_shared(dst + c * 16);
            asm volatile("cp.async.cg.shared.global [%0], [%1], 16;\n" :: "r"(sp), "l"(g));
        }
        if (tid < 128) {                                  // chunks 256..383
            int c = tid + 256;
            const char* g = src1 + (c - 192) * 16;
            unsigned sp = (unsigned)__cvta_generic_to_shared(dst + c * 16);
            asm volatile("cp.async.cg.shared.global [%0], [%1], 16;\n" :: "r"(sp), "l"(g));
        }
    };

    #pragma unroll
    for (int p = 0; p < LOOKAHEAD; p++) {
        issue_stage(p);
        asm volatile("cp.async.commit_group;\n" ::: "memory");
    }

    // per-row constants + carry in registers
    const float lw0 = lw[n * 3 + 0], lw1 = lw[n * 3 + 1], lw2 = lw[n * 3 + 2];
    const float lbn = lb[n];
    const float* up = u_begin + ((size_t)n * NN + tid) * 3;
    float u0 = up[0], u1 = up[1], u2 = up[2];
    float* op = out + (size_t)n * NN + tid;

    for (int s = 0; s < SS; s++) {
        __syncthreads();                                   // stage (s-1) reads done block-wide
        if (s + LOOKAHEAD < SS) issue_stage(s + LOOKAHEAD);
        asm volatile("cp.async.commit_group;\n" ::: "memory");          // empty groups near tail keep accounting uniform
        asm volatile("cp.async.wait_group %0;\n" :: "n"(LOOKAHEAD) : "memory");  // stage s landed (this thread's part)
        __syncthreads();                                   // stage s landed for ALL threads

        const float* st0 = stages[s % NSTAGE];
        const float* st1 = st0 + NN * 3;
        float a00 = st0[3 * tid], a01 = st0[3 * tid + 1], a02 = st0[3 * tid + 2];
        float a10 = st1[3 * tid], a11 = st1[3 * tid + 1], a12 = st1[3 * tid + 2];

        const float f0 = Fs[2 * s];
        const float f1 = Fs[2 * s + 1];

        float l0 = u0 + a00 * f0 + a10 * f1;
        float l1 = u1 + a01 * f0 + a11 * f1;
        float l2 = u2 + a02 * f0 + a12 * f1;

        float mx = fmaxf(l0, fmaxf(l1, l2));
        float e0 = __expf(l0 - mx);
        float e1 = __expf(l1 - mx);
        float e2 = __expf(l2 - mx);
        float inv = __fdividef(1.0f, e0 + e1 + e2);

        u0 = e0 * inv;
        u1 = e1 * inv;
        u2 = e2 * inv;

        op[(size_t)s * NN * NN] = u0 * lw0 + u1 * lw1 + u2 * lw2 + lbn;
    }
}

extern "C" void kernel_launch(void* const* d_in, const int* in_sizes, int n_in,
                              void* d_out, int out_size)
{
    const float* time    = (const float*)d_in[0];   // [2]
    const float* ev      = (const float*)d_in[1];   // [201,256,256]
    const float* u_begin = (const float*)d_in[2];   // [256,256,3]
    const float* a       = (const float*)d_in[3];   // [200,256,256,3]
    const float* w       = (const float*)d_in[4];   // [200,256,1,256]
    const float* lw      = (const float*)d_in[5];   // [256,3]
    const float* lb      = (const float*)d_in[6];   // [256]

    float* out = (float*)d_out;                     // [100,256,256]

    f_kernel<<<(TT * NN) / 8, 256>>>(time, ev, w);
    scan_kernel<<<NN, 256>>>(u_begin, a, lw, lb, out);
}

// round 4
// speedup vs baseline: 1.2287x; 1.0310x over previous
#include <cuda_runtime.h>

#define NN 256
#define TT 200
#define SS 100
#define CH 64                         // columns per scan CTA
#define NSTAGE 6
#define STAGE_FLOATS (CH * 3 * 2)     // 384 floats = 1536 B per stage
#define LOOKAHEAD 5

// F[n][t] scratch, transposed so scan CTAs read their row contiguously
__device__ float gF[NN * TT];

// ---------------- Kernel 1: F[n][t] = exp(-dot(w[t,n,:], ev[t,n,:]) * time[t&1]) ----------------
// One warp computes two adjacent-n dots (8 independent LDG.128 in flight).
__global__ __launch_bounds__(256)
void f_kernel(const float* __restrict__ time,
              const float* __restrict__ ev,
              const float* __restrict__ w)
{
    const int p    = blockIdx.x * 8 + (threadIdx.x >> 5);   // pair index 0..25599
    const int lane = threadIdx.x & 31;
    const int t  = p >> 7;            // 0..199
    const int n0 = (p & 127) * 2;     // 0,2,..,254

    const float4* wa = (const float4*)(w  + ((size_t)t * NN + n0) * NN);
    const float4* ea = (const float4*)(ev + ((size_t)t * NN + n0) * NN);
    const float4* wb = wa + (NN / 4);
    const float4* eb = ea + (NN / 4);

    // issue all 8 loads before any dependent math
    float4 w0 = wa[lane],      w1 = wa[lane + 32];
    float4 e0 = ea[lane],      e1 = ea[lane + 32];
    float4 w2 = wb[lane],      w3 = wb[lane + 32];
    float4 e2 = eb[lane],      e3 = eb[lane + 32];

    float accA = w0.x*e0.x + w0.y*e0.y + w0.z*e0.z + w0.w*e0.w
               + w1.x*e1.x + w1.y*e1.y + w1.z*e1.z + w1.w*e1.w;
    float accB = w2.x*e2.x + w2.y*e2.y + w2.z*e2.z + w2.w*e2.w
               + w3.x*e3.x + w3.y*e3.y + w3.z*e3.z + w3.w*e3.w;
    #pragma unroll
    for (int off = 16; off; off >>= 1) {
        accA += __shfl_xor_sync(0xffffffffu, accA, off);
        accB += __shfl_xor_sync(0xffffffffu, accB, off);
    }
    if (lane == 0) {
        const float tt = (t & 1) ? time[1] : time[0];
        gF[(size_t)n0 * TT + t]       = __expf(-accA * tt);
        gF[(size_t)(n0 + 1) * TT + t] = __expf(-accB * tt);
    }
}

// ---------------- Kernel 2: sequential scan, 1024 CTAs x 64 threads ----------------
__global__ __launch_bounds__(64)
void scan_kernel(const float* __restrict__ u_begin,
                 const float* __restrict__ a,
                 const float* __restrict__ lw,
                 const float* __restrict__ lb,
                 float* __restrict__ out)
{
    __shared__ float stages[NSTAGE][STAGE_FLOATS];   // 9216 B
    __shared__ float Fs[TT];                         // 800 B

    const int n   = blockIdx.x >> 2;          // row (node)
    const int c0  = (blockIdx.x & 3) * CH;    // column chunk base
    const int tid = threadIdx.x;              // 0..63

    // pull this row's F factors (L2-resident after f_kernel)
    for (int t = tid; t < TT; t += CH) Fs[t] = gF[(size_t)n * TT + t];

    const size_t slice = (size_t)NN * NN * 3;                   // floats per t
    const float* abase = a + ((size_t)n * NN + c0) * 3;         // a[0,n,c0,0]

    // stage s holds a[2s,n,c0:c0+64,:] ++ a[2s+1,...]  (96 x 16B chunks)
    auto issue_stage = [&](int s) {
        float* dst = stages[s % NSTAGE];
        const float* s0 = abase + (size_t)(2 * s)     * slice;  // 768 B (48 chunks)
        const float* s1 = abase + (size_t)(2 * s + 1) * slice;  // 768 B (48 chunks)
        {
            const float* g = (tid < 48) ? (s0 + tid * 4) : (s1 + (tid - 48) * 4);
            unsigned sp = (unsigned)__cvta_generic_to_shared(dst + tid * 4);
            asm volatile("cp.async.cg.shared.global [%0], [%1], 16;\n" :: "r"(sp), "l"(g));
        }
        if (tid < 32) {
            const float* g = s1 + (tid + 16) * 4;
            unsigned sp = (unsigned)__cvta_generic_to_shared(dst + (tid + 64) * 4);
            asm volatile("cp.async.cg.shared.global [%0], [%1], 16;\n" :: "r"(sp), "l"(g));
        }
    };

    #pragma unroll
    for (int p = 0; p < LOOKAHEAD; p++) {
        issue_stage(p);
        asm volatile("cp.async.commit_group;\n" ::: "memory");
    }
    asm volatile("cp.async.wait_group %0;\n" :: "n"(LOOKAHEAD - 1) : "memory"); // stage 0 (this thread)
    __syncthreads();                                                            // stage 0 (all threads)

    // per-row constants + carry in registers
    const float lw0 = lw[n * 3 + 0], lw1 = lw[n * 3 + 1], lw2 = lw[n * 3 + 2];
    const float lbn = lb[n];
    const float* up = u_begin + ((size_t)n * NN + c0 + tid) * 3;
    float u0 = up[0], u1 = up[1], u2 = up[2];
    float* op = out + (size_t)n * NN + c0 + tid;

    for (int s = 0; s < SS; s++) {
        // stage s is fully resident (end-of-previous-iteration wait + barrier)
        const float* st0 = stages[s % NSTAGE];
        const float* st1 = st0 + CH * 3;
        const float a00 = st0[3 * tid], a01 = st0[3 * tid + 1], a02 = st0[3 * tid + 2];
        const float a10 = st1[3 * tid], a11 = st1[3 * tid + 1], a12 = st1[3 * tid + 2];

        const float f0 = Fs[2 * s];
        const float f1 = Fs[2 * s + 1];

        float l0 = u0 + a00 * f0 + a10 * f1;
        float l1 = u1 + a01 * f0 + a11 * f1;
        float l2 = u2 + a02 * f0 + a12 * f1;

        float mx = fmaxf(l0, fmaxf(l1, l2));
        float e0 = __expf(l0 - mx);
        float e1 = __expf(l1 - mx);
        float e2 = __expf(l2 - mx);
        float inv = __fdividef(1.0f, e0 + e1 + e2);

        u0 = e0 * inv;
        u1 = e1 * inv;
        u2 = e2 * inv;

        op[(size_t)s * NN * NN] = u0 * lw0 + u1 * lw1 + u2 * lw2 + lbn;

        // refill the ring: overwrites buffer of stage s-1 (reads done after barrier)
        if (s + LOOKAHEAD < SS) issue_stage(s + LOOKAHEAD);
        asm volatile("cp.async.commit_group;\n" ::: "memory");                  // (empty near tail)
        asm volatile("cp.async.wait_group %0;\n" :: "n"(LOOKAHEAD - 1) : "memory"); // stage s+1 here
        __syncthreads();                                                        // stage s+1 everywhere
    }
}

extern "C" void kernel_launch(void* const* d_in, const int* in_sizes, int n_in,
                              void* d_out, int out_size)
{
    const float* time    = (const float*)d_in[0];   // [2]
    const float* ev      = (const float*)d_in[1];   // [201,256,256]
    const float* u_begin = (const float*)d_in[2];   // [256,256,3]
    const float* a       = (const float*)d_in[3];   // [200,256,256,3]
    const float* w       = (const float*)d_in[4];   // [200,256,1,256]
    const float* lw      = (const float*)d_in[5];   // [256,3]
    const float* lb      = (const float*)d_in[6];   // [256]

    float* out = (float*)d_out;                     // [100,256,256]

    f_kernel<<<(TT * NN / 2) / 8, 256>>>(time, ev, w);
    scan_kernel<<<NN * 4, CH>>>(u_begin, a, lw, lb, out);
}